// round 1
// baseline (speedup 1.0000x reference)
#include <cuda_runtime.h>

// Problem constants (fixed shapes from reference):
//   x: [8, 2048, 1024] f32 -> M=16384 rows, C=1024 channels
//   U: [1024, 1024] f32, perm: [1024] i32, randint: [1] i32
namespace {
constexpr int M = 8 * 2048;   // 16384
constexpr int C = 1024;
constexpr float RAND_SCALE = 1.0f / 3.0f;  // sqrt(0.1/0.9) == 1/3 exactly
}

// Scratch (allocation-free rule: __device__ globals)
__device__ float g_xg[(size_t)M * C];  // gathered x  (64 MB)
__device__ float g_y [(size_t)M * C];  // y = xg @ U  (64 MB)

// ---------------------------------------------------------------------------
// Stage 1: per-row gather.  xg[r][i] = x[r][(perm[i]*m_r) & 1023]
// One block per row; stage the row in smem so both global read and write are
// fully coalesced; the random access happens in shared memory.
// ---------------------------------------------------------------------------
__global__ void __launch_bounds__(256)
gather_kernel(const float* __restrict__ x,
              const int*   __restrict__ perm,
              const int*   __restrict__ randint) {
    __shared__ float sx[C];
    const unsigned r    = blockIdx.x;
    const unsigned mult = ((unsigned)randint[0] * 6u) & 1023u;
    const unsigned m    = (mult * r + 1u) & 1023u;   // always odd -> bijection

    const float* xr  = x    + (size_t)r * C;
    float*       xgr = g_xg + (size_t)r * C;

    #pragma unroll
    for (int i = threadIdx.x; i < C; i += 256) sx[i] = xr[i];
    __syncthreads();

    #pragma unroll
    for (int i = threadIdx.x; i < C; i += 256) {
        unsigned a = ((unsigned)perm[i] * m) & 1023u;
        xgr[i] = sx[a];
    }
}

// ---------------------------------------------------------------------------
// Stage 2: y = xg @ U.   M=16384, N=1024, K=1024, all f32.
// Classic 128x128x16 block tile, 256 threads, 8x8 register micro-tile,
// A stored transposed in smem (padded), float4 global + smem accesses.
// ---------------------------------------------------------------------------
namespace {
constexpr int BM = 128, BN = 128, BK = 16, TM = 8, TN = 8;
constexpr int APAD = 4;  // pad transposed-A rows to kill store conflicts, keep 16B align
}

__global__ void __launch_bounds__(256)
sgemm_kernel(const float* __restrict__ B /* = U, [K][N] row-major */) {
    __shared__ float As[BK][BM + APAD];
    __shared__ float Bs[BK][BN];

    const int bx  = blockIdx.x;   // N tile (0..7)
    const int by  = blockIdx.y;   // M tile (0..127)
    const int tid = threadIdx.x;
    const int tx  = tid & 15;     // 0..15
    const int ty  = tid >> 4;     // 0..15

    const float* Ag = g_xg + (size_t)by * BM * C;
    const float* Bg = B + bx * BN;

    float acc[TM][TN] = {};

    // A-load mapping: 128 rows x 16 cols = 2048 f32 -> 2 float4 per thread
    const int arow = tid >> 2;          // 0..63
    const int acol = (tid & 3) * 4;     // {0,4,8,12}
    // B-load mapping: 16 rows x 128 cols -> 2 float4 per thread
    const int brow = tid >> 5;          // 0..7
    const int bcol = (tid & 31) * 4;    // 0..124

    for (int k0 = 0; k0 < C; k0 += BK) {
        #pragma unroll
        for (int i = 0; i < 2; i++) {
            const int r = arow + i * 64;
            float4 v = *reinterpret_cast<const float4*>(Ag + (size_t)r * C + k0 + acol);
            As[acol + 0][r] = v.x;
            As[acol + 1][r] = v.y;
            As[acol + 2][r] = v.z;
            As[acol + 3][r] = v.w;
        }
        #pragma unroll
        for (int i = 0; i < 2; i++) {
            const int r = brow + i * 8;
            float4 v = *reinterpret_cast<const float4*>(Bg + (size_t)(k0 + r) * C + bcol);
            *reinterpret_cast<float4*>(&Bs[r][bcol]) = v;
        }
        __syncthreads();

        #pragma unroll
        for (int k = 0; k < BK; k++) {
            float4 a0 = *reinterpret_cast<const float4*>(&As[k][ty * TM]);
            float4 a1 = *reinterpret_cast<const float4*>(&As[k][ty * TM + 4]);
            float4 b0 = *reinterpret_cast<const float4*>(&Bs[k][tx * TN]);
            float4 b1 = *reinterpret_cast<const float4*>(&Bs[k][tx * TN + 4]);
            float ra[TM] = {a0.x, a0.y, a0.z, a0.w, a1.x, a1.y, a1.z, a1.w};
            float rb[TN] = {b0.x, b0.y, b0.z, b0.w, b1.x, b1.y, b1.z, b1.w};
            #pragma unroll
            for (int i = 0; i < TM; i++)
                #pragma unroll
                for (int j = 0; j < TN; j++)
                    acc[i][j] = fmaf(ra[i], rb[j], acc[i][j]);
        }
        __syncthreads();
    }

    // Write y tile (coalesced float4)
    #pragma unroll
    for (int i = 0; i < TM; i++) {
        float* Crow = g_y + (size_t)(by * BM + ty * TM + i) * C + bx * BN + tx * TN;
        *reinterpret_cast<float4*>(Crow)     = make_float4(acc[i][0], acc[i][1], acc[i][2], acc[i][3]);
        *reinterpret_cast<float4*>(Crow + 4) = make_float4(acc[i][4], acc[i][5], acc[i][6], acc[i][7]);
    }
}

// ---------------------------------------------------------------------------
// Stage 3: scatter + residual.  out[r][a_r(i)] = y[r][i]/3 + x[r][a_r(i)]
// Stage the scattered row in smem (random writes to smem, coalesced global IO).
// ---------------------------------------------------------------------------
__global__ void __launch_bounds__(256)
scatter_kernel(const float* __restrict__ x,
               const int*   __restrict__ perm,
               const int*   __restrict__ randint,
               float*       __restrict__ out) {
    __shared__ float so[C];
    const unsigned r    = blockIdx.x;
    const unsigned mult = ((unsigned)randint[0] * 6u) & 1023u;
    const unsigned m    = (mult * r + 1u) & 1023u;

    const float* yr = g_y + (size_t)r * C;

    #pragma unroll
    for (int i = threadIdx.x; i < C; i += 256) {
        unsigned a = ((unsigned)perm[i] * m) & 1023u;
        so[a] = yr[i];
    }
    __syncthreads();

    const float* xr = x   + (size_t)r * C;
    float*       orow = out + (size_t)r * C;
    #pragma unroll
    for (int i = threadIdx.x; i < C; i += 256) {
        orow[i] = fmaf(so[i], RAND_SCALE, xr[i]);
    }
}

// ---------------------------------------------------------------------------
// Launch (graph-capturable: kernel launches only, default stream)
// ---------------------------------------------------------------------------
extern "C" void kernel_launch(void* const* d_in, const int* in_sizes, int n_in,
                              void* d_out, int out_size) {
    const float* x       = (const float*)d_in[0];
    const float* U       = (const float*)d_in[1];
    const int*   perm    = (const int*)d_in[2];
    const int*   randint = (const int*)d_in[3];
    float*       out     = (float*)d_out;

    gather_kernel<<<M, 256>>>(x, perm, randint);

    dim3 grid(C / BN, M / BM);  // (8, 128)
    sgemm_kernel<<<grid, 256>>>(U);

    scatter_kernel<<<M, 256>>>(x, perm, randint, out);
}

// round 3
// speedup vs baseline: 2.4557x; 2.4557x over previous
#include <cuda_runtime.h>
#include <cstdint>

// ===========================================================================
// GaussProjDrop: x[16384,1024] f32; per-row perm a_r(i) = (perm[i]*m_r) & 1023
// with m_r = (6*randint*r + 1) & 1023 (odd -> bijection, n = 2^10).
//   y = gather(x) @ U;  out = scatter(y) * (1/3) + x
// Pipeline: gather(+tf32 RNA round) -> U tf32 round -> mma.sync tf32 GEMM -> scatter+axpy
// (tcgen05 is unreachable: harness gencode targets compute_103, not compute_103a)
// ===========================================================================

namespace {
constexpr int M = 8 * 2048;   // 16384
constexpr int C = 1024;
constexpr float RAND_SCALE = 1.0f / 3.0f;   // sqrt(0.1/0.9) exactly

// GEMM tiling
constexpr int BM = 128, BN = 128, BK = 32;
constexpr int NKT = C / BK;                 // 32 k-tiles
constexpr int STAGES = 3;
constexpr int ASM_F = BK + 4;               // 36 floats per A smem row (pad 4)
constexpr int BSM_F = BN + 8;               // 136 floats per B smem row (pad 8)
constexpr int A_SM_BYTES = BM * ASM_F * 4;  // 18432
constexpr int B_SM_BYTES = BK * BSM_F * 4;  // 17408
constexpr int STAGE_BYTES = A_SM_BYTES + B_SM_BYTES;   // 35840
constexpr int GSMEM = STAGES * STAGE_BYTES;            // 107520
}

// Scratch (__device__ globals: allocation-free rule)
__device__ float g_xg[(size_t)M * C];   // gathered x, tf32-rounded (64 MB)
__device__ float g_ur[(size_t)C * C];   // U, tf32-rounded           (4 MB)
__device__ float g_y [(size_t)M * C];   // y = xg @ U                (64 MB)

// ---------------------------------------------------------------------------
__device__ __forceinline__ float tf32_rna(float x) {
    uint32_t u;
    asm("cvt.rna.tf32.f32 %0, %1;" : "=r"(u) : "f"(x));
    return __uint_as_float(u);
}
__device__ __forceinline__ void cp_async16(uint32_t dst, const void* src) {
    asm volatile("cp.async.cg.shared.global [%0], [%1], 16;" :: "r"(dst), "l"(src));
}
__device__ __forceinline__ uint32_t smem_u32(const void* p) {
    uint32_t a;
    asm("{ .reg .u64 t; cvta.to.shared.u64 t, %1; cvt.u32.u64 %0, t; }" : "=r"(a) : "l"(p));
    return a;
}
__device__ __forceinline__ void mma_tf32(float c[4], const uint32_t a[4], const uint32_t b[2]) {
    asm volatile(
        "mma.sync.aligned.m16n8k8.row.col.f32.tf32.tf32.f32 "
        "{%0,%1,%2,%3}, {%4,%5,%6,%7}, {%8,%9}, {%0,%1,%2,%3};"
        : "+f"(c[0]), "+f"(c[1]), "+f"(c[2]), "+f"(c[3])
        : "r"(a[0]), "r"(a[1]), "r"(a[2]), "r"(a[3]), "r"(b[0]), "r"(b[1]));
}

// ---------------------------------------------------------------------------
// Stage 1: per-row gather + tf32 rounding.  xg[r][i] = tf32(x[r][(perm[i]*m_r)&1023])
// ---------------------------------------------------------------------------
__global__ void __launch_bounds__(256)
gather_kernel(const float* __restrict__ x,
              const int*   __restrict__ perm,
              const int*   __restrict__ randint) {
    __shared__ float sx[C];
    const unsigned r    = blockIdx.x;
    const unsigned mult = ((unsigned)randint[0] * 6u) & 1023u;
    const unsigned m    = (mult * r + 1u) & 1023u;

    const float* xr  = x    + (size_t)r * C;
    float*       xgr = g_xg + (size_t)r * C;

    for (int i = threadIdx.x; i < C; i += 256) sx[i] = xr[i];
    __syncthreads();
    for (int i = threadIdx.x; i < C; i += 256) {
        unsigned a = ((unsigned)perm[i] * m) & 1023u;
        xgr[i] = tf32_rna(sx[a]);
    }
}

// ---------------------------------------------------------------------------
// Stage 1b: g_ur = tf32_rna(U)   (no transpose: mma.sync B is col-major kxn,
// and U[k][n] row-major is exactly that)
// ---------------------------------------------------------------------------
__global__ void __launch_bounds__(256)
uround_kernel(const float* __restrict__ U) {
    int i = (blockIdx.x * 256 + threadIdx.x) * 4;
    float4 v = *reinterpret_cast<const float4*>(U + i);
    v.x = tf32_rna(v.x); v.y = tf32_rna(v.y);
    v.z = tf32_rna(v.z); v.w = tf32_rna(v.w);
    *reinterpret_cast<float4*>(g_ur + i) = v;
}

// ---------------------------------------------------------------------------
// Stage 2: y = xg @ U via mma.sync tf32 (m16n8k8).
// CTA 128x128x32, 256 thr, warps 2(m) x 4(n), warp tile 64x32.
// ---------------------------------------------------------------------------
__device__ __forceinline__ void fill_stage(int f, int tid, uint32_t smb, int by, int bx) {
    const int s = f % STAGES;
    const uint32_t a_base = smb + s * STAGE_BYTES;
    const uint32_t b_base = a_base + A_SM_BYTES;
    const float* Ag = g_xg + (size_t)(by * BM) * C + f * BK;
    const float* Bg = g_ur + (size_t)(f * BK) * C + bx * BN;
    #pragma unroll
    for (int i = 0; i < 4; i++) {               // A: 128 rows x 8 chunks
        int id = tid + i * 256;
        int r = id >> 3, c = id & 7;
        cp_async16(a_base + (r * ASM_F + c * 4) * 4, Ag + (size_t)r * C + c * 4);
    }
    #pragma unroll
    for (int i = 0; i < 4; i++) {               // B: 32 rows x 32 chunks
        int id = tid + i * 256;
        int r = id >> 5, c = id & 31;
        cp_async16(b_base + (r * BSM_F + c * 4) * 4, Bg + (size_t)r * C + c * 4);
    }
    asm volatile("cp.async.commit_group;" ::: "memory");
}

__global__ void __launch_bounds__(256, 2)
gemm_kernel() {
    extern __shared__ char smem[];
    const uint32_t smb = smem_u32(smem);

    const int bx  = blockIdx.x;       // 0..7   (N tiles)
    const int by  = blockIdx.y;       // 0..127 (M tiles)
    const int tid = threadIdx.x;
    const int wid = tid >> 5, lane = tid & 31;
    const int wm  = wid & 1;          // 0..1
    const int wn  = wid >> 1;         // 0..3
    const int qid = lane >> 2;        // 0..7  (groupID)
    const int tq  = lane & 3;         // 0..3  (thread in group)

    float acc[4][4][4];               // [m-tile][n-tile][frag]
    #pragma unroll
    for (int i = 0; i < 4; i++)
        #pragma unroll
        for (int j = 0; j < 4; j++)
            #pragma unroll
            for (int q = 0; q < 4; q++) acc[i][j][q] = 0.f;

    // Prologue
    #pragma unroll
    for (int f = 0; f < STAGES - 1; f++) fill_stage(f, tid, smb, by, bx);

    for (int kt = 0; kt < NKT; kt++) {
        asm volatile("cp.async.wait_group %0;" :: "n"(STAGES - 2) : "memory");
        __syncthreads();

        const int f = kt + STAGES - 1;
        if (f < NKT) fill_stage(f, tid, smb, by, bx);   // fills slot freed last iter

        const int s = kt % STAGES;
        const float* As = reinterpret_cast<const float*>(smem + s * STAGE_BYTES);
        const float* Bs = reinterpret_cast<const float*>(smem + s * STAGE_BYTES + A_SM_BYTES);

        #pragma unroll
        for (int ks = 0; ks < 4; ks++) {
            const int k8 = ks * 8;
            uint32_t afr[4][4], bfr[4][2];
            #pragma unroll
            for (int mt = 0; mt < 4; mt++) {
                const float* ap = As + (wm * 64 + mt * 16 + qid) * ASM_F + k8 + tq;
                afr[mt][0] = __float_as_uint(ap[0]);
                afr[mt][1] = __float_as_uint(ap[8 * ASM_F]);
                afr[mt][2] = __float_as_uint(ap[4]);
                afr[mt][3] = __float_as_uint(ap[8 * ASM_F + 4]);
            }
            #pragma unroll
            for (int nt = 0; nt < 4; nt++) {
                const float* bp = Bs + (k8 + tq) * BSM_F + wn * 32 + nt * 8 + qid;
                bfr[nt][0] = __float_as_uint(bp[0]);
                bfr[nt][1] = __float_as_uint(bp[4 * BSM_F]);
            }
            #pragma unroll
            for (int mt = 0; mt < 4; mt++)
                #pragma unroll
                for (int nt = 0; nt < 4; nt++)
                    mma_tf32(acc[mt][nt], afr[mt], bfr[nt]);
        }
        __syncthreads();
    }

    // Epilogue: c0,c1 at (row, 2*tq), c2,c3 at (row+8, 2*tq)
    #pragma unroll
    for (int mt = 0; mt < 4; mt++) {
        const int row = by * BM + wm * 64 + mt * 16 + qid;
        #pragma unroll
        for (int nt = 0; nt < 4; nt++) {
            const int col = bx * BN + wn * 32 + nt * 8 + 2 * tq;
            float* p0 = g_y + (size_t)row * C + col;
            *reinterpret_cast<float2*>(p0)            = make_float2(acc[mt][nt][0], acc[mt][nt][1]);
            *reinterpret_cast<float2*>(p0 + 8 * C)    = make_float2(acc[mt][nt][2], acc[mt][nt][3]);
        }
    }
}

// ---------------------------------------------------------------------------
// Stage 3: scatter + residual.  out[r][a(i)] = y[r][i]/3 + x[r][a(i)]
// ---------------------------------------------------------------------------
__global__ void __launch_bounds__(256)
scatter_kernel(const float* __restrict__ x,
               const int*   __restrict__ perm,
               const int*   __restrict__ randint,
               float*       __restrict__ out) {
    __shared__ float so[C];
    const unsigned r    = blockIdx.x;
    const unsigned mult = ((unsigned)randint[0] * 6u) & 1023u;
    const unsigned m    = (mult * r + 1u) & 1023u;

    const float* yr = g_y + (size_t)r * C;
    for (int i = threadIdx.x; i < C; i += 256) {
        unsigned a = ((unsigned)perm[i] * m) & 1023u;
        so[a] = yr[i];
    }
    __syncthreads();
    const float* xr = x + (size_t)r * C;
    float* orow = out + (size_t)r * C;
    for (int i = threadIdx.x; i < C; i += 256)
        orow[i] = fmaf(so[i], RAND_SCALE, xr[i]);
}

// ---------------------------------------------------------------------------
extern "C" void kernel_launch(void* const* d_in, const int* in_sizes, int n_in,
                              void* d_out, int out_size) {
    const float* x       = (const float*)d_in[0];
    const float* U       = (const float*)d_in[1];
    const int*   perm    = (const int*)d_in[2];
    const int*   randint = (const int*)d_in[3];
    float*       out     = (float*)d_out;

    static bool attr_done = false;
    if (!attr_done) {
        cudaFuncSetAttribute(gemm_kernel,
                             cudaFuncAttributeMaxDynamicSharedMemorySize, GSMEM);
        attr_done = true;
    }

    gather_kernel<<<M, 256>>>(x, perm, randint);
    uround_kernel<<<(C * C) / (256 * 4), 256>>>(U);
    gemm_kernel<<<dim3(C / BN, M / BM), 256, GSMEM>>>();
    scatter_kernel<<<M, 256>>>(x, perm, randint, out);
}

// round 4
// speedup vs baseline: 5.5759x; 2.2706x over previous
#include <cuda_runtime.h>
#include <cuda_fp16.h>
#include <cstdint>

// ===========================================================================
// GaussProjDrop: x[16384,1024] f32; per-row perm a_r(i) = (perm[i]*m_r) & 1023,
// m_r = (6*randint*r + 1) & 1023 (odd -> bijection since n = 2^10).
//   y = gather(x) @ U;  out = scatter(y) * (1/3) + x
// fp16 mma.sync GEMM (fp16 u = 2^-11 == tf32, but 2x the MMA rate).
// ===========================================================================

namespace {
constexpr int M = 8 * 2048;   // 16384
constexpr int C = 1024;
constexpr float RAND_SCALE = 1.0f / 3.0f;

constexpr int BM = 128, BN = 128, BK = 64;
constexpr int NKT = C / BK;                  // 16 k-tiles
constexpr int STAGES = 3;
constexpr int A_SM_BYTES = BM * BK * 2;      // 16384 (row = 128 B, 8 x 16B chunks)
constexpr int B_SM_BYTES = BK * BN * 2;      // 16384 (row = 256 B, 16 x 16B chunks)
constexpr int STAGE_BYTES = A_SM_BYTES + B_SM_BYTES;   // 32768
constexpr int GSMEM = STAGES * STAGE_BYTES;            // 98304
}

// Scratch (__device__ globals: allocation-free rule)
__device__ __half g_xg[(size_t)M * C];   // gathered x, fp16 (32 MB)
__device__ __half g_uh[(size_t)C * C];   // U, fp16            (2 MB)
__device__ float  g_y [(size_t)M * C];   // y = xg @ U         (64 MB)

// ---------------------------------------------------------------------------
__device__ __forceinline__ void cp_async16(uint32_t dst, const void* src) {
    asm volatile("cp.async.cg.shared.global [%0], [%1], 16;" :: "r"(dst), "l"(src));
}
__device__ __forceinline__ uint32_t smem_u32(const void* p) {
    uint32_t a;
    asm("{ .reg .u64 t; cvta.to.shared.u64 t, %1; cvt.u32.u64 %0, t; }" : "=r"(a) : "l"(p));
    return a;
}
__device__ __forceinline__ void ldsm_x4(uint32_t r[4], uint32_t addr) {
    asm volatile("ldmatrix.sync.aligned.m8n8.x4.shared.b16 {%0,%1,%2,%3}, [%4];"
                 : "=r"(r[0]), "=r"(r[1]), "=r"(r[2]), "=r"(r[3]) : "r"(addr));
}
__device__ __forceinline__ void ldsm_x4_t(uint32_t r[4], uint32_t addr) {
    asm volatile("ldmatrix.sync.aligned.m8n8.x4.trans.shared.b16 {%0,%1,%2,%3}, [%4];"
                 : "=r"(r[0]), "=r"(r[1]), "=r"(r[2]), "=r"(r[3]) : "r"(addr));
}
__device__ __forceinline__ void mma_f16(float c[4], const uint32_t a[4], uint32_t b0, uint32_t b1) {
    asm volatile(
        "mma.sync.aligned.m16n8k16.row.col.f32.f16.f16.f32 "
        "{%0,%1,%2,%3}, {%4,%5,%6,%7}, {%8,%9}, {%0,%1,%2,%3};"
        : "+f"(c[0]), "+f"(c[1]), "+f"(c[2]), "+f"(c[3])
        : "r"(a[0]), "r"(a[1]), "r"(a[2]), "r"(a[3]), "r"(b0), "r"(b1));
}

// ---------------------------------------------------------------------------
// Stage 1: per-row gather -> fp16.  xg[r][i] = f16(x[r][(perm[i]*m_r)&1023])
// 4 rows per 256-thread block, float4 global loads.
// ---------------------------------------------------------------------------
__global__ void __launch_bounds__(256)
gather_kernel(const float* __restrict__ x,
              const int*   __restrict__ perm,
              const int*   __restrict__ randint) {
    __shared__ float sx[4][C];
    const int r0 = blockIdx.x * 4;
    const unsigned mult = ((unsigned)randint[0] * 6u) & 1023u;
    const int tid = threadIdx.x;

    // load 4 rows = 1024 float4 chunks
    #pragma unroll
    for (int i = 0; i < 4; i++) {
        int id = tid + i * 256;                 // 0..1023
        int rr = id >> 8, c4 = (id & 255) * 4;
        *reinterpret_cast<float4*>(&sx[rr][c4]) =
            *reinterpret_cast<const float4*>(x + (size_t)(r0 + rr) * C + c4);
    }
    __syncthreads();

    // permuted read -> fp16 write (half2)
    #pragma unroll
    for (int i = 0; i < 8; i++) {
        int id = tid + i * 256;                 // 0..2047 (half2 units)
        int rr = id >> 9, j = (id & 511) * 2;
        unsigned m = (mult * (unsigned)(r0 + rr) + 1u) & 1023u;
        unsigned a0 = ((unsigned)perm[j]     * m) & 1023u;
        unsigned a1 = ((unsigned)perm[j + 1] * m) & 1023u;
        __half2 h = __floats2half2_rn(sx[rr][a0], sx[rr][a1]);
        *reinterpret_cast<__half2*>(g_xg + (size_t)(r0 + rr) * C + j) = h;
    }
}

// ---------------------------------------------------------------------------
// Stage 1b: g_uh = f16(U)
// ---------------------------------------------------------------------------
__global__ void __launch_bounds__(256)
uconv_kernel(const float* __restrict__ U) {
    int i = (blockIdx.x * 256 + threadIdx.x) * 4;
    float4 v = *reinterpret_cast<const float4*>(U + i);
    __half2 h0 = __floats2half2_rn(v.x, v.y);
    __half2 h1 = __floats2half2_rn(v.z, v.w);
    *reinterpret_cast<__half2*>(g_uh + i)     = h0;
    *reinterpret_cast<__half2*>(g_uh + i + 2) = h1;
}

// ---------------------------------------------------------------------------
// Stage 2: y = xg @ U, fp16 mma.sync m16n8k16, fp32 accum.
// CTA 128x128x64, 256 thr, warps 2(m)x4(n), warp tile 64x32.
// Smem: A rows 128B (8x16B chunks), B rows 256B (16x16B chunks), xor-8 swizzle.
// ---------------------------------------------------------------------------
__device__ __forceinline__ void fill_stage(int f, int tid, uint32_t smb, int by, int bx) {
    const int s = f % STAGES;
    const uint32_t a_base = smb + s * STAGE_BYTES;
    const uint32_t b_base = a_base + A_SM_BYTES;
    const __half* Ag = g_xg + (size_t)(by * BM) * C + f * BK;
    const __half* Bg = g_uh + (size_t)(f * BK) * C + bx * BN;
    #pragma unroll
    for (int i = 0; i < 4; i++) {               // A: 128 rows x 8 chunks
        int id = tid + i * 256;
        int r = id >> 3, c = id & 7;
        cp_async16(a_base + r * 128 + ((c ^ (r & 7)) << 4), Ag + (size_t)r * C + c * 8);
    }
    #pragma unroll
    for (int i = 0; i < 4; i++) {               // B: 64 rows x 16 chunks
        int id = tid + i * 256;
        int r = id >> 4, c = id & 15;
        cp_async16(b_base + r * 256 + ((c ^ (r & 7)) << 4), Bg + (size_t)r * C + c * 8);
    }
    asm volatile("cp.async.commit_group;" ::: "memory");
}

__global__ void __launch_bounds__(256, 2)
gemm_kernel() {
    extern __shared__ char smem[];
    const uint32_t smb = smem_u32(smem);

    const int bx  = blockIdx.x;       // 0..7
    const int by  = blockIdx.y;       // 0..127
    const int tid = threadIdx.x;
    const int wid = tid >> 5, lane = tid & 31;
    const int wm  = wid & 1;          // 0..1
    const int wn  = wid >> 1;         // 0..3
    const int l7   = lane & 7;
    const int seg1 = (lane >> 3) & 1;  // +8 rows
    const int seg2 = lane >> 4;        // second k/n chunk

    float acc[4][4][4];
    #pragma unroll
    for (int i = 0; i < 4; i++)
        #pragma unroll
        for (int j = 0; j < 4; j++)
            #pragma unroll
            for (int q = 0; q < 4; q++) acc[i][j][q] = 0.f;

    #pragma unroll
    for (int f = 0; f < STAGES - 1; f++) fill_stage(f, tid, smb, by, bx);

    // Per-lane invariants for ldmatrix addressing
    const int a_rowloc = wm * 64 + l7 + seg1 * 8;     // + mt*16
    const int b_kloc   = l7 + seg1 * 8;               // + ks*16
    const int b_ccbase = wn * 4 + seg2;               // + nb*2 (chunk idx, xor l7)

    for (int kt = 0; kt < NKT; kt++) {
        asm volatile("cp.async.wait_group %0;" :: "n"(STAGES - 2) : "memory");
        __syncthreads();

        const int f = kt + STAGES - 1;
        if (f < NKT) fill_stage(f, tid, smb, by, bx);

        const int s = kt % STAGES;
        const uint32_t As = smb + s * STAGE_BYTES;
        const uint32_t Bs = As + A_SM_BYTES;

        #pragma unroll
        for (int ks = 0; ks < 4; ks++) {
            uint32_t afr[4][4], bfr[2][4];
            const int a_chunk = 2 * ks + seg2;                     // 0..7
            #pragma unroll
            for (int mt = 0; mt < 4; mt++) {
                uint32_t addr = As + (a_rowloc + mt * 16) * 128 + ((a_chunk ^ l7) << 4);
                ldsm_x4(afr[mt], addr);
            }
            const int bk = ks * 16 + b_kloc;                       // k row
            #pragma unroll
            for (int nb = 0; nb < 2; nb++) {
                uint32_t addr = Bs + bk * 256 + (((b_ccbase + nb * 2) ^ l7) << 4);
                ldsm_x4_t(bfr[nb], addr);
            }
            #pragma unroll
            for (int mt = 0; mt < 4; mt++)
                #pragma unroll
                for (int nt = 0; nt < 4; nt++)
                    mma_f16(acc[mt][nt], afr[mt],
                            bfr[nt >> 1][2 * (nt & 1)], bfr[nt >> 1][2 * (nt & 1) + 1]);
        }
        __syncthreads();
    }

    // Epilogue: c0,c1 @ (g, 2t), c2,c3 @ (g+8, 2t)
    const int qid = lane >> 2, tq = lane & 3;
    #pragma unroll
    for (int mt = 0; mt < 4; mt++) {
        const int row = by * BM + wm * 64 + mt * 16 + qid;
        #pragma unroll
        for (int nt = 0; nt < 4; nt++) {
            const int col = bx * BN + wn * 32 + nt * 8 + 2 * tq;
            float* p0 = g_y + (size_t)row * C + col;
            *reinterpret_cast<float2*>(p0)         = make_float2(acc[mt][nt][0], acc[mt][nt][1]);
            *reinterpret_cast<float2*>(p0 + 8 * C) = make_float2(acc[mt][nt][2], acc[mt][nt][3]);
        }
    }
}

// ---------------------------------------------------------------------------
// Stage 3: scatter + residual.  out[r][a(i)] = y[r][i]/3 + x[r][a(i)]
// 8 rows per 512-thread block, float4 IO.
// ---------------------------------------------------------------------------
__global__ void __launch_bounds__(512)
scatter_kernel(const float* __restrict__ x,
               const int*   __restrict__ perm,
               const int*   __restrict__ randint,
               float*       __restrict__ out) {
    __shared__ float so[8][C];
    const int r0 = blockIdx.x * 8;
    const unsigned mult = ((unsigned)randint[0] * 6u) & 1023u;
    const int tid = threadIdx.x;

    // Phase 1: linear read of y, scattered store into smem
    #pragma unroll
    for (int i = 0; i < 4; i++) {
        int id = tid + i * 512;                  // 0..2047 float4 chunks
        int rr = id >> 8, j = (id & 255) * 4;
        unsigned m = (mult * (unsigned)(r0 + rr) + 1u) & 1023u;
        float4 v = *reinterpret_cast<const float4*>(g_y + (size_t)(r0 + rr) * C + j);
        so[rr][((unsigned)perm[j]     * m) & 1023u] = v.x;
        so[rr][((unsigned)perm[j + 1] * m) & 1023u] = v.y;
        so[rr][((unsigned)perm[j + 2] * m) & 1023u] = v.z;
        so[rr][((unsigned)perm[j + 3] * m) & 1023u] = v.w;
    }
    __syncthreads();

    // Phase 2: coalesced out = so/3 + x
    #pragma unroll
    for (int i = 0; i < 4; i++) {
        int id = tid + i * 512;
        int rr = id >> 8, j = (id & 255) * 4;
        const size_t off = (size_t)(r0 + rr) * C + j;
        float4 xv = *reinterpret_cast<const float4*>(x + off);
        float4 o;
        o.x = fmaf(so[rr][j],     RAND_SCALE, xv.x);
        o.y = fmaf(so[rr][j + 1], RAND_SCALE, xv.y);
        o.z = fmaf(so[rr][j + 2], RAND_SCALE, xv.z);
        o.w = fmaf(so[rr][j + 3], RAND_SCALE, xv.w);
        *reinterpret_cast<float4*>(out + off) = o;
    }
}

// ---------------------------------------------------------------------------
extern "C" void kernel_launch(void* const* d_in, const int* in_sizes, int n_in,
                              void* d_out, int out_size) {
    const float* x       = (const float*)d_in[0];
    const float* U       = (const float*)d_in[1];
    const int*   perm    = (const int*)d_in[2];
    const int*   randint = (const int*)d_in[3];
    float*       out     = (float*)d_out;

    static bool attr_done = false;
    if (!attr_done) {
        cudaFuncSetAttribute(gemm_kernel,
                             cudaFuncAttributeMaxDynamicSharedMemorySize, GSMEM);
        attr_done = true;
    }

    gather_kernel<<<M / 4, 256>>>(x, perm, randint);
    uconv_kernel<<<(C * C) / (256 * 4), 256>>>(U);
    gemm_kernel<<<dim3(C / BN, M / BM), 256, GSMEM>>>();
    scatter_kernel<<<M / 8, 512>>>(x, perm, randint, out);
}